// round 15
// baseline (speedup 1.0000x reference)
#include <cuda_runtime.h>
#include <cuda_bf16.h>

// SymmetryConstraint — closed form per (batch, class) group (u = x - 0.5):
//   sum_{i<j}(u_i+u_j)^2 = (m-2)*sum(u^2) + (sum u)^2
//   sum_{i<j}(y_i-y_j)^2 = m*sum(y^2) - (sum y)^2
//   pairs = m*(m-1)/2
//
// R15: champion R14 (128 blocks x 256 threads, 2 batches/block, 4 pts/lane,
// ONE fused u64 atomic per block, REDUX.SYNC counts, branchless combine)
// with a 3-LDG front: each thread owns 4 CONSECUTIVE points ->
// one int4 class load + two adjacent float4 coord loads (same bytes, one
// fewer LSU issue per thread).
// Fused word: bits[0:30) loss (2^-7 fixed pt), [30:56) pair count,
// [56:64) arrivals. Winner computes out[] from the atomic return value;
// atomicExch reset => graph-replay safe. Commutative integer adds =>
// bit-deterministic under any block arrival order.

#define NPTS    512
#define NBATCH  256
#define TPB     256
#define BPB     2
#define NBLOCKS (NBATCH / BPB)   // 128

#define LOSS_BITS 30
#define CNT_SHIFT 30
#define ARR_SHIFT 56
#define LOSS_SCALE 128.0f

__device__ unsigned long long g_all = 0ull;

__global__ __launch_bounds__(TPB)
void symconstraint_kernel(const float* __restrict__ kp,   // [B, N, 2] f32
                          const int*   __restrict__ cls,  // [B, N]    i32
                          float*       __restrict__ out)  // [1]
{
    const int t    = threadIdx.x;
    const int warp = t >> 5;            // 0..7
    const int lane = t & 31;
    const int batch_local = warp >> 2;  // 0..1
    const int wib         = warp & 3;
    const int batch       = blockIdx.x * BPB + batch_local;

    const float4* __restrict__ kp4  = reinterpret_cast<const float4*>(kp);
    const int4*   __restrict__ cls4 = reinterpret_cast<const int4*>(cls);

    // Each thread owns 4 consecutive points: p0 = 4*(wib*32 + lane).
    const int tix  = wib * 32 + lane;          // 0..127 within batch
    const int cidx = batch * (NPTS / 4) + tix; // int4 index (128 per row)
    const int fidx = batch * (NPTS / 2) + 2 * tix; // float4 index (256 per row)

    const int4   c4 = cls4[cidx];
    const float4 q0 = kp4 [fidx];       // points p0, p0+1
    const float4 q1 = kp4 [fidx + 1];   // points p0+2, p0+3

    float su[3]  = {0.f, 0.f, 0.f};
    float su2[3] = {0.f, 0.f, 0.f};
    float sy[3]  = {0.f, 0.f, 0.f};
    float sy2[3] = {0.f, 0.f, 0.f};
    int   cntp   = 0;   // 3 x 10-bit packed counts

    #pragma unroll
    for (int p = 0; p < 4; p++) {
        const int   c  = (p == 0) ? c4.x : (p == 1) ? c4.y : (p == 2) ? c4.z : c4.w;
        const float xx = (p == 0) ? q0.x : (p == 1) ? q0.z : (p == 2) ? q1.x : q1.z;
        const float yy = (p == 0) ? q0.y : (p == 1) ? q0.w : (p == 2) ? q1.y : q1.w;
        const float u  = xx - 0.5f;
        const float uu = u * u;
        const float y2 = yy * yy;
        #pragma unroll
        for (int k = 0; k < 3; k++) {
            const bool h = (c == k);
            su[k]  += h ? u  : 0.f;
            su2[k] += h ? uu : 0.f;
            sy[k]  += h ? yy : 0.f;
            sy2[k] += h ? y2 : 0.f;
        }
        const unsigned uc = (unsigned)c;
        cntp += (uc <= 2u) ? (1 << (10u * (uc & 3u))) : 0;
    }

    // Warp reduce: 12 float butterflies (5 levels) + 1 hardware int redux.
    #pragma unroll
    for (int o = 16; o > 0; o >>= 1) {
        #pragma unroll
        for (int k = 0; k < 3; k++) {
            su[k]  += __shfl_xor_sync(0xffffffffu, su[k],  o);
            su2[k] += __shfl_xor_sync(0xffffffffu, su2[k], o);
            sy[k]  += __shfl_xor_sync(0xffffffffu, sy[k],  o);
            sy2[k] += __shfl_xor_sync(0xffffffffu, sy2[k], o);
        }
    }
    cntp = __reduce_add_sync(0xffffffffu, cntp);

    __shared__ float s_acc[8][12];
    __shared__ int   s_cnt[8];

    if (lane == 0) {
        #pragma unroll
        for (int k = 0; k < 3; k++) {
            s_acc[warp][k]     = su[k];
            s_acc[warp][3 + k] = su2[k];
            s_acc[warp][6 + k] = sy[k];
            s_acc[warp][9 + k] = sy2[k];
        }
        s_cnt[warp] = cntp;
    }
    __syncthreads();

    // Warp 0 finishes: lanes 0/1 combine one batch's 4 warps each, branchless
    // closed form, fold lane 1 -> lane 0, lane 0 publishes the fused atomic.
    if (warp == 0) {
        float loss = 0.f;
        int   pc   = 0;
        if (lane < BPB) {
            const int w0 = lane * 4;
            float a[12];
            #pragma unroll
            for (int j = 0; j < 12; j++)
                a[j] = (s_acc[w0][j] + s_acc[w0 + 1][j])
                     + (s_acc[w0 + 2][j] + s_acc[w0 + 3][j]);
            const int pk = (s_cnt[w0] + s_cnt[w0 + 1])
                         + (s_cnt[w0 + 2] + s_cnt[w0 + 3]);

            #pragma unroll
            for (int k = 0; k < 3; k++) {
                const int   mi = (pk >> (10 * k)) & 1023;
                const float m  = (float)mi;
                loss += (m - 2.f) * a[3 + k] + a[k] * a[k]
                      +  m        * a[9 + k] - a[6 + k] * a[6 + k];
                pc   += (mi * (mi - 1)) >> 1;
            }
        }
        loss += __shfl_xor_sync(0xffffffffu, loss, 1);
        pc   += __shfl_xor_sync(0xffffffffu, pc,   1);

        if (lane == 0) {
            const unsigned long long lfix =
                (unsigned long long)(loss * LOSS_SCALE + 0.5f);
            const unsigned long long mine =
                lfix
                + ((unsigned long long)pc << CNT_SHIFT)
                + (1ull << ARR_SHIFT);

            const unsigned long long ret = atomicAdd(&g_all, mine);

            if ((ret >> ARR_SHIFT) == NBLOCKS - 1) {          // we are last
                const unsigned long long tot = ret + mine;
                const float totL = (float)(tot & ((1ull << LOSS_BITS) - 1))
                                   * (1.0f / LOSS_SCALE);
                const float totC = (float)((tot >> CNT_SHIFT)
                                   & ((1ull << (ARR_SHIFT - CNT_SHIFT)) - 1));
                out[0] = totL / fmaxf(totC, 1.0f);
                atomicExch(&g_all, 0ull);                     // replay-safe reset
            }
        }
    }
}

extern "C" void kernel_launch(void* const* d_in, const int* in_sizes, int n_in,
                              void* d_out, int out_size)
{
    const float* kp  = (const float*)d_in[0];
    const int*   cls = (const int*)d_in[1];
    float*       out = (float*)d_out;

    symconstraint_kernel<<<NBLOCKS, TPB>>>(kp, cls, out);
}